// round 7
// baseline (speedup 1.0000x reference)
#include <cuda_runtime.h>

// Problem constants (match reference)
#define B_ 8
#define S_ 2048
#define N_ 512
#define D_ 1024
#define MAX_W_ 32
#define MASK_FILL_ (-1000.0f)

// Tiling
#define TILE_ 64                       // span-start bin width
#define NB_ (S_ / TILE_)               // 32 bins per batch
#define ROWS_ (TILE_ + MAX_W_ - 1)     // 95 rows covered per tile
#define CAP_ 512                       // max spans per bin (<= N)
#define NQ_ 4                          // D split into 4 quarters of 256 floats
#define QF4_ 64                        // float4 per quarter-row (256 floats)

// Dynamic smem: 95 rows x 64 float4 (97280 B) + 95 logits + pad
#define SMEM_BYTES_ (ROWS_ * QF4_ * 16 + 512)

// Device scratch (static — no allocation allowed)
__device__ float g_logits[B_ * S_];
__device__ int   g_bin_count[B_ * NB_];
__device__ int   g_bin_list[B_ * NB_ * CAP_];

// ---------------------------------------------------------------------------
__global__ void zero_bins_kernel() {
    int i = blockIdx.x * blockDim.x + threadIdx.x;
    if (i < B_ * NB_) g_bin_count[i] = 0;
}

__global__ void bin_kernel(const int* __restrict__ spans) {
    int bn = blockIdx.x * blockDim.x + threadIdx.x;
    if (bn >= B_ * N_) return;
    int b     = bn / N_;
    int start = spans[bn * 2 + 0];
    int bin   = b * NB_ + (start >> 6);          // TILE_ = 64
    int pos   = atomicAdd(&g_bin_count[bin], 1);
    g_bin_list[bin * CAP_ + pos] = bn;
}

// ---------------------------------------------------------------------------
// logits[b,s] = dot(seq[b,s,:], att_w) + att_b. One warp per row.
__global__ void __launch_bounds__(256)
logits_kernel(const float* __restrict__ seq,
              const float* __restrict__ att_w,
              const float* __restrict__ att_b) {
    int warp = (blockIdx.x * blockDim.x + threadIdx.x) >> 5;
    int lane = threadIdx.x & 31;
    if (warp >= B_ * S_) return;

    const float4* row = reinterpret_cast<const float4*>(seq + (size_t)warp * D_);
    const float4* w4  = reinterpret_cast<const float4*>(att_w);

    float acc = 0.0f;
    #pragma unroll
    for (int i = 0; i < (D_ / 4) / 32; i++) {
        float4 a = row[lane + i * 32];
        float4 w = w4[lane + i * 32];
        acc += a.x * w.x + a.y * w.y + a.z * w.z + a.w * w.w;
    }
    #pragma unroll
    for (int off = 16; off; off >>= 1)
        acc += __shfl_xor_sync(0xffffffffu, acc, off);

    if (lane == 0)
        g_logits[warp] = acc + att_b[0];
}

// ---------------------------------------------------------------------------
// Main: CTA = (batch, tile, D-quarter). Stage 95 rows x 1KB into smem once,
// then each warp pools one span from smem. Masked softmax arithmetic is
// bit-identical to reference (masked exp underflows to exactly 0).
__global__ void __launch_bounds__(512)
span_tiled_kernel(const float* __restrict__ seq,
                  const int*   __restrict__ spans,
                  float*       __restrict__ out) {
    extern __shared__ float smem[];
    float4* s_data   = reinterpret_cast<float4*>(smem);        // ROWS_ * QF4_
    float*  s_logits = smem + ROWS_ * QF4_ * 4;                // ROWS_ floats

    const int bid  = blockIdx.x;          // b * (NB_*NQ_) + tile * NQ_ + q
    const int q    = bid & (NQ_ - 1);
    const int tile = (bid >> 2) & (NB_ - 1);
    const int b    = bid >> 7;            // / (NB_ * NQ_)
    const int t0   = tile * TILE_;
    const int tid  = threadIdx.x;
    const int lane = tid & 31;
    const int wid  = tid >> 5;            // 0..15

    const int nrow = min(ROWS_, S_ - t0);

    // Stage logits tile
    if (tid < nrow)
        s_logits[tid] = g_logits[b * S_ + t0 + tid];

    // Stage sequence slab: rows [t0, t0+nrow), cols [q*256, q*256+256)
    {
        const float4* src = reinterpret_cast<const float4*>(seq)
                          + ((size_t)b * S_ + t0) * (D_ / 4) + q * QF4_;
        const int total = nrow * QF4_;
        for (int i = tid; i < total; i += 512) {
            int r = i >> 6;               // / QF4_
            int c = i & (QF4_ - 1);
            s_data[i] = src[(size_t)r * (D_ / 4) + c];
        }
    }
    __syncthreads();

    const int count = g_bin_count[b * NB_ + tile];
    const int lbase = (b * NB_ + tile) * CAP_;

    for (int task = wid; task < count; task += 16) {
        const int bn    = g_bin_list[lbase + task];
        const int start = spans[bn * 2 + 0];
        const int end   = spans[bn * 2 + 1];      // inclusive
        const int width = end - start;            // 0..31
        const bool m    = (lane <= width);

        // per-warp softmax; lane holds weight of row (start + width - lane)
        float logit = m ? s_logits[end - t0 - lane] : MASK_FILL_;
        float mx = logit;
        #pragma unroll
        for (int off = 16; off; off >>= 1)
            mx = fmaxf(mx, __shfl_xor_sync(0xffffffffu, mx, off));
        float e = m ? __expf(logit - mx) : 0.0f;
        float sum = e;
        #pragma unroll
        for (int off = 16; off; off >>= 1)
            sum += __shfl_xor_sync(0xffffffffu, sum, off);
        const float myattn = e / sum;

        // pooling from smem; lane owns float4 columns lane and lane+32
        float4 a0 = make_float4(0.f, 0.f, 0.f, 0.f);
        float4 a1 = make_float4(0.f, 0.f, 0.f, 0.f);
        const int rl0 = start - t0;                // 0..63
        const int nv  = width + 1;

        int j = 0;
        for (; j + 2 <= nv; j += 2) {
            const float wa = __shfl_sync(0xffffffffu, myattn, width - j);
            const float wb = __shfl_sync(0xffffffffu, myattn, width - j - 1);
            const float4 v0 = s_data[(rl0 + j) * QF4_ + lane];
            const float4 v1 = s_data[(rl0 + j) * QF4_ + 32 + lane];
            const float4 u0 = s_data[(rl0 + j + 1) * QF4_ + lane];
            const float4 u1 = s_data[(rl0 + j + 1) * QF4_ + 32 + lane];
            a0.x += wa*v0.x; a0.y += wa*v0.y; a0.z += wa*v0.z; a0.w += wa*v0.w;
            a1.x += wa*v1.x; a1.y += wa*v1.y; a1.z += wa*v1.z; a1.w += wa*v1.w;
            a0.x += wb*u0.x; a0.y += wb*u0.y; a0.z += wb*u0.z; a0.w += wb*u0.w;
            a1.x += wb*u1.x; a1.y += wb*u1.y; a1.z += wb*u1.z; a1.w += wb*u1.w;
        }
        if (j < nv) {
            const float wa = __shfl_sync(0xffffffffu, myattn, width - j);
            const float4 v0 = s_data[(rl0 + j) * QF4_ + lane];
            const float4 v1 = s_data[(rl0 + j) * QF4_ + 32 + lane];
            a0.x += wa*v0.x; a0.y += wa*v0.y; a0.z += wa*v0.z; a0.w += wa*v0.w;
            a1.x += wa*v1.x; a1.y += wa*v1.y; a1.z += wa*v1.z; a1.w += wa*v1.w;
        }

        float4* o = reinterpret_cast<float4*>(out)
                  + (size_t)bn * (D_ / 4) + q * QF4_ + lane;
        o[0]  = a0;
        o[32] = a1;
    }
}

// ---------------------------------------------------------------------------
extern "C" void kernel_launch(void* const* d_in, const int* in_sizes, int n_in,
                              void* d_out, int out_size) {
    const float* seq   = (const float*)d_in[0];   // (B, S, D) f32
    const int*   spans = (const int*)  d_in[1];   // (B, N, 2) i32
    const float* att_w = (const float*)d_in[2];   // (D, 1) f32
    const float* att_b = (const float*)d_in[3];   // (1,) f32
    float* out = (float*)d_out;                   // (B, N, D) f32

    cudaFuncSetAttribute(span_tiled_kernel,
                         cudaFuncAttributeMaxDynamicSharedMemorySize,
                         SMEM_BYTES_);

    zero_bins_kernel<<<1, 256>>>();
    bin_kernel<<<(B_ * N_) / 256, 256>>>(spans);
    logits_kernel<<<(B_ * S_) / 8, 256>>>(seq, att_w, att_b);
    span_tiled_kernel<<<B_ * NB_ * NQ_, 512, SMEM_BYTES_>>>(seq, spans, out);
}

// round 9
// speedup vs baseline: 1.2241x; 1.2241x over previous
#include <cuda_runtime.h>

// Problem constants (match reference)
#define B_ 8
#define S_ 2048
#define N_ 512
#define D_ 1024
#define MAX_W_ 32
#define MASK_FILL_ (-1000.0f)

// Scratch for global attention logits (B*S floats = 64 KB).
__device__ float g_logits[B_ * S_];

// packed f32x2 FMA: acc = v * w + acc  (two floats at once)
__device__ __forceinline__ void fma2(unsigned long long& acc,
                                     unsigned long long v,
                                     unsigned long long w) {
    asm("fma.rn.f32x2 %0, %1, %2, %0;" : "+l"(acc) : "l"(v), "l"(w));
}
// broadcast one float into both halves of an f32x2 register pair
__device__ __forceinline__ unsigned long long pack2(float a) {
    unsigned long long r;
    asm("mov.b64 %0, {%1, %1};" : "=l"(r) : "r"(__float_as_uint(a)));
    return r;
}

// ---------------------------------------------------------------------------
// Kernel 1: logits[b,s] = dot(seq[b,s,:], att_w) + att_b. One warp per row.
__global__ void __launch_bounds__(256)
logits_kernel(const float* __restrict__ seq,
              const float* __restrict__ att_w,
              const float* __restrict__ att_b) {
    int warp = (blockIdx.x * blockDim.x + threadIdx.x) >> 5;
    int lane = threadIdx.x & 31;
    if (warp >= B_ * S_) return;

    const float4* row = reinterpret_cast<const float4*>(seq + (size_t)warp * D_);
    const float4* w4  = reinterpret_cast<const float4*>(att_w);

    float acc = 0.0f;
    #pragma unroll
    for (int i = 0; i < (D_ / 4) / 32; i++) {
        float4 a = row[lane + i * 32];
        float4 w = w4[lane + i * 32];
        acc += a.x * w.x + a.y * w.y + a.z * w.z + a.w * w.w;
    }
    #pragma unroll
    for (int off = 16; off; off >>= 1)
        acc += __shfl_xor_sync(0xffffffffu, acc, off);

    if (lane == 0)
        g_logits[warp] = acc + att_b[0];
}

// ---------------------------------------------------------------------------
// Kernel 2: one CTA (256 threads) per span; thread owns one 16B (4-float)
// column chunk. A row of D=1024 floats = 256 such chunks, so the chunk
// stride between consecutive rows is RCHUNK = D/4 = 256.
// Every warp computes the softmax redundantly (no smem, no __syncthreads, no
// serial warp0 prefix). Masked lanes contribute exp()==0 exactly, identical
// arithmetic to the reference. Pooling uses packed f32x2 FMAs; weight for
// ascending row j lives in lane (width - j) and is fetched by shuffle.
#define RCHUNK_ (D_ / 4)   // 16B chunks per row = 256

__global__ void __launch_bounds__(256)
span_kernel(const float* __restrict__ seq,
            const int*   __restrict__ spans,
            float*       __restrict__ out) {
    const int bn   = blockIdx.x;          // 0 .. B*N-1
    const int b    = bn >> 9;             // / N_ (N_ = 512)
    const int tid  = threadIdx.x;
    const int lane = tid & 31;

    const int start = __ldg(&spans[bn * 2 + 0]);
    const int end   = __ldg(&spans[bn * 2 + 1]);   // inclusive
    const int width = end - start;                 // 0..31
    const bool m    = (lane <= width);

    // --- per-warp softmax (lane t <-> position end - t) ---
    float logit = m ? g_logits[b * S_ + end - lane] : MASK_FILL_;
    float mx = logit;
    #pragma unroll
    for (int off = 16; off; off >>= 1)
        mx = fmaxf(mx, __shfl_xor_sync(0xffffffffu, mx, off));
    float e = m ? __expf(logit - mx) : 0.0f;
    float sum = e;
    #pragma unroll
    for (int off = 16; off; off >>= 1)
        sum += __shfl_xor_sync(0xffffffffu, sum, off);
    const float myattn = e / sum;   // weight of row (start + width - lane)

    // --- pooling: rows [start .. end], ascending ---
    const ulonglong2* base = reinterpret_cast<const ulonglong2*>(seq)
                           + ((size_t)b * S_ + start) * RCHUNK_ + tid;

    unsigned long long accx = 0ull, accy = 0ull;   // (c0,c1) and (c2,c3)

    const int nv = width + 1;
    int j = 0;
    for (; j + 4 <= nv; j += 4) {
        ulonglong2 v0 = base[(size_t)(j + 0) * RCHUNK_];
        ulonglong2 v1 = base[(size_t)(j + 1) * RCHUNK_];
        ulonglong2 v2 = base[(size_t)(j + 2) * RCHUNK_];
        ulonglong2 v3 = base[(size_t)(j + 3) * RCHUNK_];
        unsigned long long w0 = pack2(__shfl_sync(0xffffffffu, myattn, width - j));
        unsigned long long w1 = pack2(__shfl_sync(0xffffffffu, myattn, width - j - 1));
        unsigned long long w2 = pack2(__shfl_sync(0xffffffffu, myattn, width - j - 2));
        unsigned long long w3 = pack2(__shfl_sync(0xffffffffu, myattn, width - j - 3));
        fma2(accx, v0.x, w0); fma2(accy, v0.y, w0);
        fma2(accx, v1.x, w1); fma2(accy, v1.y, w1);
        fma2(accx, v2.x, w2); fma2(accy, v2.y, w2);
        fma2(accx, v3.x, w3); fma2(accy, v3.y, w3);
    }
    for (; j < nv; j++) {
        ulonglong2 v = base[(size_t)j * RCHUNK_];
        unsigned long long w = pack2(__shfl_sync(0xffffffffu, myattn, width - j));
        fma2(accx, v.x, w); fma2(accy, v.y, w);
    }

    ulonglong2 res;
    res.x = accx;
    res.y = accy;
    reinterpret_cast<ulonglong2*>(out)[(size_t)bn * RCHUNK_ + tid] = res;
}

// ---------------------------------------------------------------------------
extern "C" void kernel_launch(void* const* d_in, const int* in_sizes, int n_in,
                              void* d_out, int out_size) {
    const float* seq   = (const float*)d_in[0];   // (B, S, D) f32
    const int*   spans = (const int*)  d_in[1];   // (B, N, 2) i32
    const float* att_w = (const float*)d_in[2];   // (D, 1) f32
    const float* att_b = (const float*)d_in[3];   // (1,) f32
    float* out = (float*)d_out;                   // (B, N, D) f32

    logits_kernel<<<(B_ * S_) / 8, 256>>>(seq, att_w, att_b);
    span_kernel<<<B_ * N_, 256>>>(seq, spans, out);
}